// round 1
// baseline (speedup 1.0000x reference)
#include <cuda_runtime.h>
#include <math.h>

#define B_SZ   16384
#define C_CAM  4
#define DBB    2048
#define DH     512
#define MTOT   (B_SZ * C_CAM)   // 65536

// -------- scratch (device globals: no allocations allowed) --------
__device__ float g_reg[(size_t)MTOT * DH];   // proj output
__device__ float g_xn [(size_t)MTOT * DH];   // layernormed
__device__ float g_h  [(size_t)MTOT * DH];   // swiglu output
__device__ float g_A  [(size_t)MTOT * 36];   // lie algebra (pre-skew)

// -------- helpers --------
__device__ __forceinline__ unsigned f2tf(float x) {
    unsigned u;
    asm("cvt.rna.tf32.f32 %0, %1;" : "=r"(u) : "f"(x));
    return u;
}

__device__ __forceinline__ void mma_tf32(float d[4], const unsigned a[4], const unsigned b[2]) {
    asm volatile(
        "mma.sync.aligned.m16n8k8.row.col.f32.tf32.tf32.f32 "
        "{%0,%1,%2,%3}, {%4,%5,%6,%7}, {%8,%9}, {%0,%1,%2,%3};\n"
        : "+f"(d[0]), "+f"(d[1]), "+f"(d[2]), "+f"(d[3])
        : "r"(a[0]), "r"(a[1]), "r"(a[2]), "r"(a[3]),
          "r"(b[0]), "r"(b[1]));
}

// =====================================================================
// Stage 1: reg[M=65536, 512] = thumbnails[M, 2048] @ proj_w[512, 2048]^T + bias
// Tiles: BM=128, BN=128, BK=32.  8 warps as 2x4, warp tile 64x32.
// =====================================================================
__global__ __launch_bounds__(256) void gemm1_kernel(
    const float* __restrict__ T, const float* __restrict__ W,
    const float* __restrict__ bias)
{
    const int LDS_ = 36;  // BK=32 + pad 4
    __shared__ unsigned As[128 * 36];
    __shared__ unsigned Bs[128 * 36];

    int tid  = threadIdx.x;
    int bm   = blockIdx.y * 128;
    int bn   = blockIdx.x * 128;
    int warp = tid >> 5, lane = tid & 31;
    int wr = warp >> 2, wc = warp & 3;       // 2 x 4 warp grid
    int wm = wr * 64,  wn = wc * 32;
    int g = lane >> 2, t = lane & 3;

    float acc[4][4][4];
    #pragma unroll
    for (int i = 0; i < 4; i++)
        #pragma unroll
        for (int j = 0; j < 4; j++)
            #pragma unroll
            for (int k = 0; k < 4; k++) acc[i][j][k] = 0.f;

    int lrow = tid >> 3;            // 0..31
    int lcol = (tid & 7) * 4;       // 0..28

    for (int k0 = 0; k0 < DBB; k0 += 32) {
        #pragma unroll
        for (int it = 0; it < 4; it++) {
            int r = lrow + it * 32;
            float4 v = *(const float4*)(T + (size_t)(bm + r) * DBB + k0 + lcol);
            unsigned* dst = &As[r * LDS_ + lcol];
            dst[0] = f2tf(v.x); dst[1] = f2tf(v.y); dst[2] = f2tf(v.z); dst[3] = f2tf(v.w);
        }
        #pragma unroll
        for (int it = 0; it < 4; it++) {
            int r = lrow + it * 32;
            float4 v = *(const float4*)(W + (size_t)(bn + r) * DBB + k0 + lcol);
            unsigned* dst = &Bs[r * LDS_ + lcol];
            dst[0] = f2tf(v.x); dst[1] = f2tf(v.y); dst[2] = f2tf(v.z); dst[3] = f2tf(v.w);
        }
        __syncthreads();

        #pragma unroll
        for (int kk = 0; kk < 32; kk += 8) {
            unsigned afr[4][4], bfr[4][2];
            #pragma unroll
            for (int mt = 0; mt < 4; mt++) {
                int r0 = wm + mt * 16;
                afr[mt][0] = As[(r0 + g    ) * LDS_ + kk + t];
                afr[mt][1] = As[(r0 + 8 + g) * LDS_ + kk + t];
                afr[mt][2] = As[(r0 + g    ) * LDS_ + kk + t + 4];
                afr[mt][3] = As[(r0 + 8 + g) * LDS_ + kk + t + 4];
            }
            #pragma unroll
            for (int nt = 0; nt < 4; nt++) {
                int n0 = wn + nt * 8;
                bfr[nt][0] = Bs[(n0 + g) * LDS_ + kk + t];
                bfr[nt][1] = Bs[(n0 + g) * LDS_ + kk + t + 4];
            }
            #pragma unroll
            for (int mt = 0; mt < 4; mt++)
                #pragma unroll
                for (int nt = 0; nt < 4; nt++)
                    mma_tf32(acc[mt][nt], afr[mt], bfr[nt]);
        }
        __syncthreads();
    }

    #pragma unroll
    for (int mt = 0; mt < 4; mt++) {
        #pragma unroll
        for (int nt = 0; nt < 4; nt++) {
            int row0 = bm + wm + mt * 16 + g;
            int col  = bn + wn + nt * 8 + t * 2;
            float b0 = bias[col], b1 = bias[col + 1];
            g_reg[(size_t)row0 * DH + col]       = acc[mt][nt][0] + b0;
            g_reg[(size_t)row0 * DH + col + 1]   = acc[mt][nt][1] + b1;
            g_reg[(size_t)(row0 + 8) * DH + col]     = acc[mt][nt][2] + b0;
            g_reg[(size_t)(row0 + 8) * DH + col + 1] = acc[mt][nt][3] + b1;
        }
    }
}

// =====================================================================
// Stage 2: per-row LayerNorm (warp per row), affine with per-camera gamma/beta
// =====================================================================
__global__ __launch_bounds__(256) void ln_kernel(
    const float* __restrict__ gamma, const float* __restrict__ beta)
{
    int wglob = (blockIdx.x * blockDim.x + threadIdx.x) >> 5;
    int lane  = threadIdx.x & 31;
    if (wglob >= MTOT) return;
    int c = wglob & 3;
    const float* row = g_reg + (size_t)wglob * DH;
    float v[16], s = 0.f, s2 = 0.f;
    #pragma unroll
    for (int i = 0; i < 16; i++) {
        v[i] = row[lane + i * 32];
        s += v[i]; s2 += v[i] * v[i];
    }
    #pragma unroll
    for (int o = 16; o > 0; o >>= 1) {
        s  += __shfl_xor_sync(0xffffffffu, s,  o);
        s2 += __shfl_xor_sync(0xffffffffu, s2, o);
    }
    float mu   = s * (1.f / DH);
    float var  = s2 * (1.f / DH) - mu * mu;
    float rstd = rsqrtf(var + 1e-5f);
    float* orow = g_xn + (size_t)wglob * DH;
    const float* ga = gamma + c * DH;
    const float* be = beta  + c * DH;
    #pragma unroll
    for (int i = 0; i < 16; i++) {
        int k = lane + i * 32;
        orow[k] = (v[i] - mu) * rstd * ga[k] + be[k];
    }
}

// =====================================================================
// Stage 3: per-camera dual GEMM + SwiGLU.
// gate/val[16384, 512] = xn_c[16384, 512] @ Wg/Wv[c][512,512]^T ; h = silu(g)*v
// A rows strided by 4 (camera interleave). BM=128, BN=64, BK=32.
// 8 warps as 4x2, warp tile 32x32 (2 mtiles x 4 ntiles, two accum sets).
// =====================================================================
__global__ __launch_bounds__(256) void gemm2_kernel(
    const float* __restrict__ Wg, const float* __restrict__ Wv)
{
    const int LDS_ = 36;
    __shared__ unsigned As [128 * 36];
    __shared__ unsigned Bgs[ 64 * 36];
    __shared__ unsigned Bvs[ 64 * 36];

    int tid  = threadIdx.x;
    int bm   = blockIdx.y * 128;     // logical row (b index)
    int bn   = blockIdx.x * 64;      // f
    int c    = blockIdx.z;
    int warp = tid >> 5, lane = tid & 31;
    int wr = warp >> 1, wc = warp & 1;   // 4 x 2
    int wm = wr * 32,  wn = wc * 32;
    int g = lane >> 2, t = lane & 3;

    float accg[2][4][4], accv[2][4][4];
    #pragma unroll
    for (int i = 0; i < 2; i++)
        #pragma unroll
        for (int j = 0; j < 4; j++)
            #pragma unroll
            for (int k = 0; k < 4; k++) { accg[i][j][k] = 0.f; accv[i][j][k] = 0.f; }

    int lrow = tid >> 3;
    int lcol = (tid & 7) * 4;
    const float* wg0 = Wg + (size_t)c * DH * DH;
    const float* wv0 = Wv + (size_t)c * DH * DH;

    for (int k0 = 0; k0 < DH; k0 += 32) {
        #pragma unroll
        for (int it = 0; it < 4; it++) {
            int r = lrow + it * 32;
            float4 v = *(const float4*)(g_xn + ((size_t)(bm + r) * 4 + c) * DH + k0 + lcol);
            unsigned* dst = &As[r * LDS_ + lcol];
            dst[0] = f2tf(v.x); dst[1] = f2tf(v.y); dst[2] = f2tf(v.z); dst[3] = f2tf(v.w);
        }
        #pragma unroll
        for (int it = 0; it < 2; it++) {
            int r = lrow + it * 32;
            float4 vg = *(const float4*)(wg0 + (size_t)(bn + r) * DH + k0 + lcol);
            float4 vv = *(const float4*)(wv0 + (size_t)(bn + r) * DH + k0 + lcol);
            unsigned* dg = &Bgs[r * LDS_ + lcol];
            unsigned* dv = &Bvs[r * LDS_ + lcol];
            dg[0] = f2tf(vg.x); dg[1] = f2tf(vg.y); dg[2] = f2tf(vg.z); dg[3] = f2tf(vg.w);
            dv[0] = f2tf(vv.x); dv[1] = f2tf(vv.y); dv[2] = f2tf(vv.z); dv[3] = f2tf(vv.w);
        }
        __syncthreads();

        #pragma unroll
        for (int kk = 0; kk < 32; kk += 8) {
            unsigned afr[2][4], bg[4][2], bv[4][2];
            #pragma unroll
            for (int mt = 0; mt < 2; mt++) {
                int r0 = wm + mt * 16;
                afr[mt][0] = As[(r0 + g    ) * LDS_ + kk + t];
                afr[mt][1] = As[(r0 + 8 + g) * LDS_ + kk + t];
                afr[mt][2] = As[(r0 + g    ) * LDS_ + kk + t + 4];
                afr[mt][3] = As[(r0 + 8 + g) * LDS_ + kk + t + 4];
            }
            #pragma unroll
            for (int nt = 0; nt < 4; nt++) {
                int n0 = wn + nt * 8;
                bg[nt][0] = Bgs[(n0 + g) * LDS_ + kk + t];
                bg[nt][1] = Bgs[(n0 + g) * LDS_ + kk + t + 4];
                bv[nt][0] = Bvs[(n0 + g) * LDS_ + kk + t];
                bv[nt][1] = Bvs[(n0 + g) * LDS_ + kk + t + 4];
            }
            #pragma unroll
            for (int mt = 0; mt < 2; mt++)
                #pragma unroll
                for (int nt = 0; nt < 4; nt++) {
                    mma_tf32(accg[mt][nt], afr[mt], bg[nt]);
                    mma_tf32(accv[mt][nt], afr[mt], bv[nt]);
                }
        }
        __syncthreads();
    }

    #pragma unroll
    for (int mt = 0; mt < 2; mt++) {
        #pragma unroll
        for (int nt = 0; nt < 4; nt++) {
            int row0 = bm + wm + mt * 16 + g;   // logical b index
            int col  = bn + wn + nt * 8 + t * 2;
            #pragma unroll
            for (int half = 0; half < 2; half++) {
                int rr = row0 + half * 8;
                float gte0 = accg[mt][nt][half * 2 + 0];
                float gte1 = accg[mt][nt][half * 2 + 1];
                float val0 = accv[mt][nt][half * 2 + 0];
                float val1 = accv[mt][nt][half * 2 + 1];
                float h0 = gte0 / (1.f + expf(-gte0)) * val0;
                float h1 = gte1 / (1.f + expf(-gte1)) * val1;
                float* dst = g_h + ((size_t)rr * 4 + c) * DH + col;
                dst[0] = h0; dst[1] = h1;
            }
        }
    }
}

// =====================================================================
// Stage 4: per-camera A[16384, 36] = h_c[16384, 512] @ w_out[c][36,512]^T
// BM=128, BN=40 (pad of 36), BK=32. 8 warps each own 16 rows (5 ntiles).
// =====================================================================
__global__ __launch_bounds__(256) void gemm3_kernel(const float* __restrict__ Wo)
{
    const int LDS_ = 36;
    __shared__ unsigned As[128 * 36];
    __shared__ unsigned Bs[ 40 * 36];

    int tid  = threadIdx.x;
    int bm   = blockIdx.y * 128;
    int c    = blockIdx.z;
    int warp = tid >> 5, lane = tid & 31;
    int wm   = warp * 16;
    int g = lane >> 2, t = lane & 3;

    float acc[5][4];
    #pragma unroll
    for (int j = 0; j < 5; j++)
        #pragma unroll
        for (int k = 0; k < 4; k++) acc[j][k] = 0.f;

    int lrow = tid >> 3;
    int lcol = (tid & 7) * 4;
    const float* wo0 = Wo + (size_t)c * 36 * DH;

    for (int k0 = 0; k0 < DH; k0 += 32) {
        #pragma unroll
        for (int it = 0; it < 4; it++) {
            int r = lrow + it * 32;
            float4 v = *(const float4*)(g_h + ((size_t)(bm + r) * 4 + c) * DH + k0 + lcol);
            unsigned* dst = &As[r * LDS_ + lcol];
            dst[0] = f2tf(v.x); dst[1] = f2tf(v.y); dst[2] = f2tf(v.z); dst[3] = f2tf(v.w);
        }
        for (int i = tid; i < 40 * 32; i += 256) {
            int r = i >> 5, cc = i & 31;
            float val = (r < 36) ? wo0[(size_t)r * DH + k0 + cc] : 0.f;
            Bs[r * LDS_ + cc] = f2tf(val);
        }
        __syncthreads();

        #pragma unroll
        for (int kk = 0; kk < 32; kk += 8) {
            unsigned afr[4], bfr[5][2];
            afr[0] = As[(wm + g    ) * LDS_ + kk + t];
            afr[1] = As[(wm + 8 + g) * LDS_ + kk + t];
            afr[2] = As[(wm + g    ) * LDS_ + kk + t + 4];
            afr[3] = As[(wm + 8 + g) * LDS_ + kk + t + 4];
            #pragma unroll
            for (int nt = 0; nt < 5; nt++) {
                int n0 = nt * 8;
                bfr[nt][0] = Bs[(n0 + g) * LDS_ + kk + t];
                bfr[nt][1] = Bs[(n0 + g) * LDS_ + kk + t + 4];
            }
            #pragma unroll
            for (int nt = 0; nt < 5; nt++)
                mma_tf32(acc[nt], afr, bfr[nt]);
        }
        __syncthreads();
    }

    #pragma unroll
    for (int nt = 0; nt < 5; nt++) {
        int col = nt * 8 + t * 2;
        if (col < 36) {
            int row0 = bm + wm + g;               // logical b index
            size_t base0 = ((size_t)row0 * 4 + c) * 36;
            size_t base1 = ((size_t)(row0 + 8) * 4 + c) * 36;
            g_A[base0 + col]     = acc[nt][0];
            g_A[base0 + col + 1] = acc[nt][1];
            g_A[base1 + col]     = acc[nt][2];
            g_A[base1 + col + 1] = acc[nt][3];
        }
    }
}

// =====================================================================
// Stage 5: skew-symmetrize, Frobenius clip, expm (scale-square, Taylor 12),
// write out[C, B, 6, 6]. One thread per matrix.
// =====================================================================
__global__ __launch_bounds__(128) void expm_kernel(float* __restrict__ out)
{
    int m = blockIdx.x * blockDim.x + threadIdx.x;
    if (m >= MTOT) return;
    int c = m & 3, b = m >> 2;

    const float* src = g_A + (size_t)m * 36;
    float raw[36];
    #pragma unroll
    for (int i = 0; i < 36; i++) raw[i] = src[i];

    float A[36]; float ss = 0.f;
    #pragma unroll
    for (int i = 0; i < 6; i++)
        #pragma unroll
        for (int j = 0; j < 6; j++) {
            float v = raw[i * 6 + j] - raw[j * 6 + i];
            A[i * 6 + j] = v; ss += v * v;
        }
    float frob  = sqrtf(ss);
    float scale = fminf(frob, 3.0f) / fmaxf(frob, 1e-8f);

    float As[36];
    #pragma unroll
    for (int i = 0; i < 36; i++) As[i] = A[i] * scale * 0.0625f;  // /16

    float E[36], term[36];
    #pragma unroll
    for (int i = 0; i < 36; i++) { E[i] = (i % 7 == 0) ? 1.f : 0.f; term[i] = E[i]; }

    #pragma unroll 1
    for (int k = 1; k <= 12; k++) {
        float nt[36];
        float inv = 1.f / (float)k;
        #pragma unroll
        for (int i = 0; i < 6; i++)
            #pragma unroll
            for (int j = 0; j < 6; j++) {
                float sacc = 0.f;
                #pragma unroll
                for (int l = 0; l < 6; l++) sacc += term[i * 6 + l] * As[l * 6 + j];
                nt[i * 6 + j] = sacc * inv;
            }
        #pragma unroll
        for (int i = 0; i < 36; i++) { term[i] = nt[i]; E[i] += nt[i]; }
    }
    #pragma unroll 1
    for (int s = 0; s < 4; s++) {
        float nt[36];
        #pragma unroll
        for (int i = 0; i < 6; i++)
            #pragma unroll
            for (int j = 0; j < 6; j++) {
                float sacc = 0.f;
                #pragma unroll
                for (int l = 0; l < 6; l++) sacc += E[i * 6 + l] * E[l * 6 + j];
                nt[i * 6 + j] = sacc;
            }
        #pragma unroll
        for (int i = 0; i < 36; i++) E[i] = nt[i];
    }

    float* dst = out + ((size_t)c * B_SZ + b) * 36;
    #pragma unroll
    for (int i = 0; i < 36; i++) dst[i] = E[i];
}

// =====================================================================
extern "C" void kernel_launch(void* const* d_in, const int* in_sizes, int n_in,
                              void* d_out, int out_size)
{
    const float* thumb  = (const float*)d_in[0];
    const float* proj_w = (const float*)d_in[1];
    const float* proj_b = (const float*)d_in[2];
    const float* gamma  = (const float*)d_in[3];
    const float* beta   = (const float*)d_in[4];
    const float* w_gate = (const float*)d_in[5];
    const float* w_val  = (const float*)d_in[6];
    const float* w_out  = (const float*)d_in[7];
    float* out = (float*)d_out;

    (void)in_sizes; (void)n_in; (void)out_size;

    gemm1_kernel<<<dim3(4, 512), 256>>>(thumb, proj_w, proj_b);
    ln_kernel<<<MTOT / 8, 256>>>(gamma, beta);
    gemm2_kernel<<<dim3(8, 128, 4), 256>>>(w_gate, w_val);
    gemm3_kernel<<<dim3(1, 128, 4), 256>>>(w_out);
    expm_kernel<<<MTOT / 128, 128>>>(out);
}

// round 2
// speedup vs baseline: 1.1976x; 1.1976x over previous
#include <cuda_runtime.h>
#include <math.h>

#define B_SZ   16384
#define C_CAM  4
#define DBB    2048
#define DH     512
#define MTOT   (B_SZ * C_CAM)   // 65536

// -------- scratch (device globals: no allocations allowed) --------
__device__ float g_reg[(size_t)MTOT * DH];   // proj output
__device__ float g_xn [(size_t)MTOT * DH];   // layernormed
__device__ float g_h  [(size_t)MTOT * DH];   // swiglu output
__device__ float g_A  [(size_t)MTOT * 36];   // lie algebra (pre-skew)

// -------- helpers --------
__device__ __forceinline__ unsigned f2tf(float x) {
    unsigned u;
    asm("cvt.rna.tf32.f32 %0, %1;" : "=r"(u) : "f"(x));
    return u;
}

__device__ __forceinline__ void mma_tf32(float d[4], const unsigned a[4], const unsigned b[2]) {
    asm volatile(
        "mma.sync.aligned.m16n8k8.row.col.f32.tf32.tf32.f32 "
        "{%0,%1,%2,%3}, {%4,%5,%6,%7}, {%8,%9}, {%0,%1,%2,%3};\n"
        : "+f"(d[0]), "+f"(d[1]), "+f"(d[2]), "+f"(d[3])
        : "r"(a[0]), "r"(a[1]), "r"(a[2]), "r"(a[3]),
          "r"(b[0]), "r"(b[1]));
}

__device__ __forceinline__ void cp16(float* s, const float* g) {
    unsigned saddr = (unsigned)__cvta_generic_to_shared(s);
    asm volatile("cp.async.cg.shared.global [%0], [%1], 16;\n" :: "r"(saddr), "l"(g));
}
__device__ __forceinline__ void cp_commit() {
    asm volatile("cp.async.commit_group;\n" ::: "memory");
}
__device__ __forceinline__ void cp_wait1() {
    asm volatile("cp.async.wait_group 1;\n" ::: "memory");
}
__device__ __forceinline__ void cp_wait0() {
    asm volatile("cp.async.wait_group 0;\n" ::: "memory");
}

#define LDS_ 36   // 32 + 4 pad (floats); row bytes = 144 (16B aligned)

// =====================================================================
// Stage 1: reg[M=65536, 512] = thumbnails[M, 2048] @ proj_w[512, 2048]^T + bias
// BM=128, BN=128, BK=32, cp.async double-buffered. 8 warps 2x4, warp 64x32.
// =====================================================================
__global__ __launch_bounds__(256, 2) void gemm1_kernel(
    const float* __restrict__ T, const float* __restrict__ W,
    const float* __restrict__ bias)
{
    extern __shared__ float sm1[];
    float* As = sm1;                 // [2][128*LDS_]
    float* Bs = sm1 + 2 * 128 * LDS_;

    int tid  = threadIdx.x;
    int bm   = blockIdx.y * 128;
    int bn   = blockIdx.x * 128;
    int warp = tid >> 5, lane = tid & 31;
    int wr = warp >> 2, wc = warp & 3;       // 2 x 4 warp grid
    int wm = wr * 64,  wn = wc * 32;
    int g = lane >> 2, t = lane & 3;

    float acc[4][4][4];
    #pragma unroll
    for (int i = 0; i < 4; i++)
        #pragma unroll
        for (int j = 0; j < 4; j++)
            #pragma unroll
            for (int k = 0; k < 4; k++) acc[i][j][k] = 0.f;

    int lrow = tid >> 3;            // 0..31
    int lcol = (tid & 7) * 4;       // 0..28

    const int NK = DBB / 32;        // 64

    // prologue: tile 0 -> buf 0
    {
        float* dA = As; float* dB = Bs;
        #pragma unroll
        for (int it = 0; it < 4; it++) {
            int r = lrow + it * 32;
            cp16(&dA[r * LDS_ + lcol], T + (size_t)(bm + r) * DBB + lcol);
            cp16(&dB[r * LDS_ + lcol], W + (size_t)(bn + r) * DBB + lcol);
        }
        cp_commit();
    }

    for (int i = 0; i < NK; i++) {
        if (i + 1 < NK) {
            int k0 = (i + 1) * 32;
            float* dA = As + ((i + 1) & 1) * 128 * LDS_;
            float* dB = Bs + ((i + 1) & 1) * 128 * LDS_;
            #pragma unroll
            for (int it = 0; it < 4; it++) {
                int r = lrow + it * 32;
                cp16(&dA[r * LDS_ + lcol], T + (size_t)(bm + r) * DBB + k0 + lcol);
                cp16(&dB[r * LDS_ + lcol], W + (size_t)(bn + r) * DBB + k0 + lcol);
            }
            cp_commit();
            cp_wait1();
        } else {
            cp_wait0();
        }
        __syncthreads();

        const float* cA = As + (i & 1) * 128 * LDS_;
        const float* cB = Bs + (i & 1) * 128 * LDS_;
        #pragma unroll
        for (int kk = 0; kk < 32; kk += 8) {
            unsigned afr[4][4], bfr[4][2];
            #pragma unroll
            for (int mt = 0; mt < 4; mt++) {
                int r0 = wm + mt * 16;
                afr[mt][0] = f2tf(cA[(r0 + g    ) * LDS_ + kk + t]);
                afr[mt][1] = f2tf(cA[(r0 + 8 + g) * LDS_ + kk + t]);
                afr[mt][2] = f2tf(cA[(r0 + g    ) * LDS_ + kk + t + 4]);
                afr[mt][3] = f2tf(cA[(r0 + 8 + g) * LDS_ + kk + t + 4]);
            }
            #pragma unroll
            for (int nt = 0; nt < 4; nt++) {
                int n0 = wn + nt * 8;
                bfr[nt][0] = f2tf(cB[(n0 + g) * LDS_ + kk + t]);
                bfr[nt][1] = f2tf(cB[(n0 + g) * LDS_ + kk + t + 4]);
            }
            #pragma unroll
            for (int mt = 0; mt < 4; mt++)
                #pragma unroll
                for (int nt = 0; nt < 4; nt++)
                    mma_tf32(acc[mt][nt], afr[mt], bfr[nt]);
        }
        __syncthreads();
    }

    #pragma unroll
    for (int mt = 0; mt < 4; mt++) {
        #pragma unroll
        for (int nt = 0; nt < 4; nt++) {
            int row0 = bm + wm + mt * 16 + g;
            int col  = bn + wn + nt * 8 + t * 2;
            float b0 = bias[col], b1 = bias[col + 1];
            g_reg[(size_t)row0 * DH + col]       = acc[mt][nt][0] + b0;
            g_reg[(size_t)row0 * DH + col + 1]   = acc[mt][nt][1] + b1;
            g_reg[(size_t)(row0 + 8) * DH + col]     = acc[mt][nt][2] + b0;
            g_reg[(size_t)(row0 + 8) * DH + col + 1] = acc[mt][nt][3] + b1;
        }
    }
}

// =====================================================================
// Stage 2: per-row LayerNorm (warp per row), affine with per-camera gamma/beta
// =====================================================================
__global__ __launch_bounds__(256) void ln_kernel(
    const float* __restrict__ gamma, const float* __restrict__ beta)
{
    int wglob = (blockIdx.x * blockDim.x + threadIdx.x) >> 5;
    int lane  = threadIdx.x & 31;
    if (wglob >= MTOT) return;
    int c = wglob & 3;
    const float* row = g_reg + (size_t)wglob * DH;
    float v[16], s = 0.f, s2 = 0.f;
    #pragma unroll
    for (int i = 0; i < 16; i++) {
        v[i] = row[lane + i * 32];
        s += v[i]; s2 += v[i] * v[i];
    }
    #pragma unroll
    for (int o = 16; o > 0; o >>= 1) {
        s  += __shfl_xor_sync(0xffffffffu, s,  o);
        s2 += __shfl_xor_sync(0xffffffffu, s2, o);
    }
    float mu   = s * (1.f / DH);
    float var  = s2 * (1.f / DH) - mu * mu;
    float rstd = rsqrtf(var + 1e-5f);
    float* orow = g_xn + (size_t)wglob * DH;
    const float* ga = gamma + c * DH;
    const float* be = beta  + c * DH;
    #pragma unroll
    for (int i = 0; i < 16; i++) {
        int k = lane + i * 32;
        orow[k] = (v[i] - mu) * rstd * ga[k] + be[k];
    }
}

// =====================================================================
// Stage 3: per-camera dual GEMM + SwiGLU, cp.async double-buffered.
// BM=128, BN=64, BK=32.  8 warps 4x2, warp 32x32, dual accumulators.
// =====================================================================
__global__ __launch_bounds__(256, 2) void gemm2_kernel(
    const float* __restrict__ Wg, const float* __restrict__ Wv)
{
    extern __shared__ float sm2[];
    float* As  = sm2;                       // [2][128*LDS_]
    float* Bgs = sm2 + 2 * 128 * LDS_;      // [2][64*LDS_]
    float* Bvs = Bgs + 2 * 64 * LDS_;       // [2][64*LDS_]

    int tid  = threadIdx.x;
    int bm   = blockIdx.y * 128;     // logical row (b index)
    int bn   = blockIdx.x * 64;      // f
    int c    = blockIdx.z;
    int warp = tid >> 5, lane = tid & 31;
    int wr = warp >> 1, wc = warp & 1;   // 4 x 2
    int wm = wr * 32,  wn = wc * 32;
    int g = lane >> 2, t = lane & 3;

    float accg[2][4][4], accv[2][4][4];
    #pragma unroll
    for (int i = 0; i < 2; i++)
        #pragma unroll
        for (int j = 0; j < 4; j++)
            #pragma unroll
            for (int k = 0; k < 4; k++) { accg[i][j][k] = 0.f; accv[i][j][k] = 0.f; }

    int lrow = tid >> 3;
    int lcol = (tid & 7) * 4;
    const float* wg0 = Wg + (size_t)c * DH * DH;
    const float* wv0 = Wv + (size_t)c * DH * DH;

    const int NK = DH / 32;   // 16

    {
        float* dA = As; float* dG = Bgs; float* dV = Bvs;
        #pragma unroll
        for (int it = 0; it < 4; it++) {
            int r = lrow + it * 32;
            cp16(&dA[r * LDS_ + lcol], g_xn + ((size_t)(bm + r) * 4 + c) * DH + lcol);
        }
        #pragma unroll
        for (int it = 0; it < 2; it++) {
            int r = lrow + it * 32;
            cp16(&dG[r * LDS_ + lcol], wg0 + (size_t)(bn + r) * DH + lcol);
            cp16(&dV[r * LDS_ + lcol], wv0 + (size_t)(bn + r) * DH + lcol);
        }
        cp_commit();
    }

    for (int i = 0; i < NK; i++) {
        if (i + 1 < NK) {
            int k0 = (i + 1) * 32;
            int b = (i + 1) & 1;
            float* dA = As  + b * 128 * LDS_;
            float* dG = Bgs + b * 64 * LDS_;
            float* dV = Bvs + b * 64 * LDS_;
            #pragma unroll
            for (int it = 0; it < 4; it++) {
                int r = lrow + it * 32;
                cp16(&dA[r * LDS_ + lcol], g_xn + ((size_t)(bm + r) * 4 + c) * DH + k0 + lcol);
            }
            #pragma unroll
            for (int it = 0; it < 2; it++) {
                int r = lrow + it * 32;
                cp16(&dG[r * LDS_ + lcol], wg0 + (size_t)(bn + r) * DH + k0 + lcol);
                cp16(&dV[r * LDS_ + lcol], wv0 + (size_t)(bn + r) * DH + k0 + lcol);
            }
            cp_commit();
            cp_wait1();
        } else {
            cp_wait0();
        }
        __syncthreads();

        int b = i & 1;
        const float* cA = As  + b * 128 * LDS_;
        const float* cG = Bgs + b * 64 * LDS_;
        const float* cV = Bvs + b * 64 * LDS_;
        #pragma unroll
        for (int kk = 0; kk < 32; kk += 8) {
            unsigned afr[2][4], bg[4][2], bv[4][2];
            #pragma unroll
            for (int mt = 0; mt < 2; mt++) {
                int r0 = wm + mt * 16;
                afr[mt][0] = f2tf(cA[(r0 + g    ) * LDS_ + kk + t]);
                afr[mt][1] = f2tf(cA[(r0 + 8 + g) * LDS_ + kk + t]);
                afr[mt][2] = f2tf(cA[(r0 + g    ) * LDS_ + kk + t + 4]);
                afr[mt][3] = f2tf(cA[(r0 + 8 + g) * LDS_ + kk + t + 4]);
            }
            #pragma unroll
            for (int nt = 0; nt < 4; nt++) {
                int n0 = wn + nt * 8;
                bg[nt][0] = f2tf(cG[(n0 + g) * LDS_ + kk + t]);
                bg[nt][1] = f2tf(cG[(n0 + g) * LDS_ + kk + t + 4]);
                bv[nt][0] = f2tf(cV[(n0 + g) * LDS_ + kk + t]);
                bv[nt][1] = f2tf(cV[(n0 + g) * LDS_ + kk + t + 4]);
            }
            #pragma unroll
            for (int mt = 0; mt < 2; mt++)
                #pragma unroll
                for (int nt = 0; nt < 4; nt++) {
                    mma_tf32(accg[mt][nt], afr[mt], bg[nt]);
                    mma_tf32(accv[mt][nt], afr[mt], bv[nt]);
                }
        }
        __syncthreads();
    }

    #pragma unroll
    for (int mt = 0; mt < 2; mt++) {
        #pragma unroll
        for (int nt = 0; nt < 4; nt++) {
            int row0 = bm + wm + mt * 16 + g;   // logical b index
            int col  = bn + wn + nt * 8 + t * 2;
            #pragma unroll
            for (int half = 0; half < 2; half++) {
                int rr = row0 + half * 8;
                float gte0 = accg[mt][nt][half * 2 + 0];
                float gte1 = accg[mt][nt][half * 2 + 1];
                float val0 = accv[mt][nt][half * 2 + 0];
                float val1 = accv[mt][nt][half * 2 + 1];
                float h0 = gte0 / (1.f + expf(-gte0)) * val0;
                float h1 = gte1 / (1.f + expf(-gte1)) * val1;
                float* dst = g_h + ((size_t)rr * 4 + c) * DH + col;
                dst[0] = h0; dst[1] = h1;
            }
        }
    }
}

// =====================================================================
// Stage 4: per-camera A[16384, 36] = h_c[16384, 512] @ w_out[c][36,512]^T
// BM=128, BN=40 (pad of 36), BK=32, cp.async double-buffered.
// =====================================================================
__global__ __launch_bounds__(256, 2) void gemm3_kernel(const float* __restrict__ Wo)
{
    extern __shared__ float sm3[];
    float* As = sm3;                  // [2][128*LDS_]
    float* Bs = sm3 + 2 * 128 * LDS_; // [2][40*LDS_]

    int tid  = threadIdx.x;
    int bm   = blockIdx.y * 128;
    int c    = blockIdx.z;
    int warp = tid >> 5, lane = tid & 31;
    int wm   = warp * 16;
    int g = lane >> 2, t = lane & 3;

    // zero the pad rows (36..39) of both B buffers once
    for (int i = tid; i < 2 * 4 * LDS_; i += 256) {
        int b = i / (4 * LDS_);
        int rem = i % (4 * LDS_);
        Bs[b * 40 * LDS_ + 36 * LDS_ + rem] = 0.f;
    }

    float acc[5][4];
    #pragma unroll
    for (int j = 0; j < 5; j++)
        #pragma unroll
        for (int k = 0; k < 4; k++) acc[j][k] = 0.f;

    int lrow = tid >> 3;
    int lcol = (tid & 7) * 4;
    const float* wo0 = Wo + (size_t)c * 36 * DH;

    const int NK = DH / 32;   // 16

    {
        #pragma unroll
        for (int it = 0; it < 4; it++) {
            int r = lrow + it * 32;
            cp16(&As[r * LDS_ + lcol], g_h + ((size_t)(bm + r) * 4 + c) * DH + lcol);
        }
        // B: 36 rows x 8 float4 cols = 288 items
        for (int i2 = tid; i2 < 288; i2 += 256) {
            int r = i2 >> 3, cc = (i2 & 7) * 4;
            cp16(&Bs[r * LDS_ + cc], wo0 + (size_t)r * DH + cc);
        }
        cp_commit();
    }

    for (int i = 0; i < NK; i++) {
        if (i + 1 < NK) {
            int k0 = (i + 1) * 32;
            int b = (i + 1) & 1;
            float* dA = As + b * 128 * LDS_;
            float* dB = Bs + b * 40 * LDS_;
            #pragma unroll
            for (int it = 0; it < 4; it++) {
                int r = lrow + it * 32;
                cp16(&dA[r * LDS_ + lcol], g_h + ((size_t)(bm + r) * 4 + c) * DH + k0 + lcol);
            }
            for (int i2 = tid; i2 < 288; i2 += 256) {
                int r = i2 >> 3, cc = (i2 & 7) * 4;
                cp16(&dB[r * LDS_ + cc], wo0 + (size_t)r * DH + k0 + cc);
            }
            cp_commit();
            cp_wait1();
        } else {
            cp_wait0();
        }
        __syncthreads();

        int b = i & 1;
        const float* cAc = As + b * 128 * LDS_;
        const float* cBc = Bs + b * 40 * LDS_;
        #pragma unroll
        for (int kk = 0; kk < 32; kk += 8) {
            unsigned afr[4], bfr[5][2];
            afr[0] = f2tf(cAc[(wm + g    ) * LDS_ + kk + t]);
            afr[1] = f2tf(cAc[(wm + 8 + g) * LDS_ + kk + t]);
            afr[2] = f2tf(cAc[(wm + g    ) * LDS_ + kk + t + 4]);
            afr[3] = f2tf(cAc[(wm + 8 + g) * LDS_ + kk + t + 4]);
            #pragma unroll
            for (int nt = 0; nt < 5; nt++) {
                int n0 = nt * 8;
                bfr[nt][0] = f2tf(cBc[(n0 + g) * LDS_ + kk + t]);
                bfr[nt][1] = f2tf(cBc[(n0 + g) * LDS_ + kk + t + 4]);
            }
            #pragma unroll
            for (int nt = 0; nt < 5; nt++)
                mma_tf32(acc[nt], afr, bfr[nt]);
        }
        __syncthreads();
    }

    #pragma unroll
    for (int nt = 0; nt < 5; nt++) {
        int col = nt * 8 + t * 2;
        if (col < 36) {
            int row0 = bm + wm + g;               // logical b index
            size_t base0 = ((size_t)row0 * 4 + c) * 36;
            size_t base1 = ((size_t)(row0 + 8) * 4 + c) * 36;
            g_A[base0 + col]     = acc[nt][0];
            g_A[base0 + col + 1] = acc[nt][1];
            g_A[base1 + col]     = acc[nt][2];
            g_A[base1 + col + 1] = acc[nt][3];
        }
    }
}

// =====================================================================
// Stage 5: skew-symmetrize, Frobenius clip, expm (scale-square, Taylor 12),
// write out[C, B, 6, 6]. One thread per matrix.
// =====================================================================
__global__ __launch_bounds__(128) void expm_kernel(float* __restrict__ out)
{
    int m = blockIdx.x * blockDim.x + threadIdx.x;
    if (m >= MTOT) return;
    int c = m & 3, b = m >> 2;

    const float* src = g_A + (size_t)m * 36;
    float raw[36];
    #pragma unroll
    for (int i = 0; i < 36; i++) raw[i] = src[i];

    float A[36]; float ss = 0.f;
    #pragma unroll
    for (int i = 0; i < 6; i++)
        #pragma unroll
        for (int j = 0; j < 6; j++) {
            float v = raw[i * 6 + j] - raw[j * 6 + i];
            A[i * 6 + j] = v; ss += v * v;
        }
    float frob  = sqrtf(ss);
    float scale = fminf(frob, 3.0f) / fmaxf(frob, 1e-8f);

    float As[36];
    #pragma unroll
    for (int i = 0; i < 36; i++) As[i] = A[i] * scale * 0.0625f;  // /16

    float E[36], term[36];
    #pragma unroll
    for (int i = 0; i < 36; i++) { E[i] = (i % 7 == 0) ? 1.f : 0.f; term[i] = E[i]; }

    #pragma unroll 1
    for (int k = 1; k <= 12; k++) {
        float nt[36];
        float inv = 1.f / (float)k;
        #pragma unroll
        for (int i = 0; i < 6; i++)
            #pragma unroll
            for (int j = 0; j < 6; j++) {
                float sacc = 0.f;
                #pragma unroll
                for (int l = 0; l < 6; l++) sacc += term[i * 6 + l] * As[l * 6 + j];
                nt[i * 6 + j] = sacc * inv;
            }
        #pragma unroll
        for (int i = 0; i < 36; i++) { term[i] = nt[i]; E[i] += nt[i]; }
    }
    #pragma unroll 1
    for (int s = 0; s < 4; s++) {
        float nt[36];
        #pragma unroll
        for (int i = 0; i < 6; i++)
            #pragma unroll
            for (int j = 0; j < 6; j++) {
                float sacc = 0.f;
                #pragma unroll
                for (int l = 0; l < 6; l++) sacc += E[i * 6 + l] * E[l * 6 + j];
                nt[i * 6 + j] = sacc;
            }
        #pragma unroll
        for (int i = 0; i < 36; i++) E[i] = nt[i];
    }

    float* dst = out + ((size_t)c * B_SZ + b) * 36;
    #pragma unroll
    for (int i = 0; i < 36; i++) dst[i] = E[i];
}

// =====================================================================
extern "C" void kernel_launch(void* const* d_in, const int* in_sizes, int n_in,
                              void* d_out, int out_size)
{
    const float* thumb  = (const float*)d_in[0];
    const float* proj_w = (const float*)d_in[1];
    const float* proj_b = (const float*)d_in[2];
    const float* gamma  = (const float*)d_in[3];
    const float* beta   = (const float*)d_in[4];
    const float* w_gate = (const float*)d_in[5];
    const float* w_val  = (const float*)d_in[6];
    const float* w_out  = (const float*)d_in[7];
    float* out = (float*)d_out;

    (void)in_sizes; (void)n_in; (void)out_size;

    const int SM1 = 2 * 128 * LDS_ * 4 * 2;                 // 73728
    const int SM2 = (2 * 128 * LDS_ + 4 * 64 * LDS_) * 4;   // 73728
    const int SM3 = (2 * 128 * LDS_ + 2 * 40 * LDS_) * 4;   // 48384

    cudaFuncSetAttribute(gemm1_kernel, cudaFuncAttributeMaxDynamicSharedMemorySize, SM1);
    cudaFuncSetAttribute(gemm2_kernel, cudaFuncAttributeMaxDynamicSharedMemorySize, SM2);
    cudaFuncSetAttribute(gemm3_kernel, cudaFuncAttributeMaxDynamicSharedMemorySize, SM3);

    gemm1_kernel<<<dim3(4, 512), 256, SM1>>>(thumb, proj_w, proj_b);
    ln_kernel<<<MTOT / 8, 256>>>(gamma, beta);
    gemm2_kernel<<<dim3(8, 128, 4), 256, SM2>>>(w_gate, w_val);
    gemm3_kernel<<<dim3(1, 128, 4), 256, SM3>>>(w_out);
    expm_kernel<<<MTOT / 128, 128>>>(out);
}

// round 3
// speedup vs baseline: 1.1994x; 1.0014x over previous
#include <cuda_runtime.h>
#include <math.h>

#define B_SZ   16384
#define C_CAM  4
#define DBB    2048
#define DH     512
#define MTOT   (B_SZ * C_CAM)   // 65536

// -------- scratch (device globals: no allocations allowed) --------
__device__ float g_reg[(size_t)MTOT * DH];   // proj output
__device__ float g_xn [(size_t)MTOT * DH];   // layernormed
__device__ float g_h  [(size_t)MTOT * DH];   // swiglu output
__device__ float g_A  [(size_t)MTOT * 36];   // lie algebra (pre-skew)

// -------- helpers --------
__device__ __forceinline__ unsigned f2tf(float x) {
    unsigned u;
    asm("cvt.rna.tf32.f32 %0, %1;" : "=r"(u) : "f"(x));
    return u;
}

__device__ __forceinline__ void mma_tf32(float d[4], const unsigned a[4], const unsigned b[2]) {
    asm volatile(
        "mma.sync.aligned.m16n8k8.row.col.f32.tf32.tf32.f32 "
        "{%0,%1,%2,%3}, {%4,%5,%6,%7}, {%8,%9}, {%0,%1,%2,%3};\n"
        : "+f"(d[0]), "+f"(d[1]), "+f"(d[2]), "+f"(d[3])
        : "r"(a[0]), "r"(a[1]), "r"(a[2]), "r"(a[3]),
          "r"(b[0]), "r"(b[1]));
}

__device__ __forceinline__ void cp16(float* s, const float* g) {
    unsigned saddr = (unsigned)__cvta_generic_to_shared(s);
    asm volatile("cp.async.cg.shared.global [%0], [%1], 16;\n" :: "r"(saddr), "l"(g));
}
__device__ __forceinline__ void cp_commit() {
    asm volatile("cp.async.commit_group;\n" ::: "memory");
}
__device__ __forceinline__ void cp_wait1() {
    asm volatile("cp.async.wait_group 1;\n" ::: "memory");
}
__device__ __forceinline__ void cp_wait0() {
    asm volatile("cp.async.wait_group 0;\n" ::: "memory");
}

#define LDS_ 36   // 32 + 4 pad (floats); row bytes = 144 (16B aligned)

// =====================================================================
// Stage 1: reg[M=65536, 512] = thumbnails[M, 2048] @ proj_w[512, 2048]^T + bias
// BM=128, BN=128, BK=32, cp.async double-buffered. 8 warps 2x4, warp 64x32.
// =====================================================================
__global__ __launch_bounds__(256, 2) void gemm1_kernel(
    const float* __restrict__ T, const float* __restrict__ W,
    const float* __restrict__ bias)
{
    extern __shared__ float sm1[];
    float* As = sm1;                 // [2][128*LDS_]
    float* Bs = sm1 + 2 * 128 * LDS_;

    int tid  = threadIdx.x;
    int bm   = blockIdx.y * 128;
    int bn   = blockIdx.x * 128;
    int warp = tid >> 5, lane = tid & 31;
    int wr = warp >> 2, wc = warp & 3;       // 2 x 4 warp grid
    int wm = wr * 64,  wn = wc * 32;
    int g = lane >> 2, t = lane & 3;

    float acc[4][4][4];
    #pragma unroll
    for (int i = 0; i < 4; i++)
        #pragma unroll
        for (int j = 0; j < 4; j++)
            #pragma unroll
            for (int k = 0; k < 4; k++) acc[i][j][k] = 0.f;

    int lrow = tid >> 3;            // 0..31
    int lcol = (tid & 7) * 4;       // 0..28

    const int NK = DBB / 32;        // 64

    // prologue: tile 0 -> buf 0
    {
        float* dA = As; float* dB = Bs;
        #pragma unroll
        for (int it = 0; it < 4; it++) {
            int r = lrow + it * 32;
            cp16(&dA[r * LDS_ + lcol], T + (size_t)(bm + r) * DBB + lcol);
            cp16(&dB[r * LDS_ + lcol], W + (size_t)(bn + r) * DBB + lcol);
        }
        cp_commit();
    }

    for (int i = 0; i < NK; i++) {
        if (i + 1 < NK) {
            int k0 = (i + 1) * 32;
            float* dA = As + ((i + 1) & 1) * 128 * LDS_;
            float* dB = Bs + ((i + 1) & 1) * 128 * LDS_;
            #pragma unroll
            for (int it = 0; it < 4; it++) {
                int r = lrow + it * 32;
                cp16(&dA[r * LDS_ + lcol], T + (size_t)(bm + r) * DBB + k0 + lcol);
                cp16(&dB[r * LDS_ + lcol], W + (size_t)(bn + r) * DBB + k0 + lcol);
            }
            cp_commit();
            cp_wait1();
        } else {
            cp_wait0();
        }
        __syncthreads();

        const float* cA = As + (i & 1) * 128 * LDS_;
        const float* cB = Bs + (i & 1) * 128 * LDS_;
        #pragma unroll
        for (int kk = 0; kk < 32; kk += 8) {
            unsigned afr[4][4], bfr[4][2];
            #pragma unroll
            for (int mt = 0; mt < 4; mt++) {
                int r0 = wm + mt * 16;
                afr[mt][0] = f2tf(cA[(r0 + g    ) * LDS_ + kk + t]);
                afr[mt][1] = f2tf(cA[(r0 + 8 + g) * LDS_ + kk + t]);
                afr[mt][2] = f2tf(cA[(r0 + g    ) * LDS_ + kk + t + 4]);
                afr[mt][3] = f2tf(cA[(r0 + 8 + g) * LDS_ + kk + t + 4]);
            }
            #pragma unroll
            for (int nt = 0; nt < 4; nt++) {
                int n0 = wn + nt * 8;
                bfr[nt][0] = f2tf(cB[(n0 + g) * LDS_ + kk + t]);
                bfr[nt][1] = f2tf(cB[(n0 + g) * LDS_ + kk + t + 4]);
            }
            #pragma unroll
            for (int mt = 0; mt < 4; mt++)
                #pragma unroll
                for (int nt = 0; nt < 4; nt++)
                    mma_tf32(acc[mt][nt], afr[mt], bfr[nt]);
        }
        __syncthreads();
    }

    #pragma unroll
    for (int mt = 0; mt < 4; mt++) {
        #pragma unroll
        for (int nt = 0; nt < 4; nt++) {
            int row0 = bm + wm + mt * 16 + g;
            int col  = bn + wn + nt * 8 + t * 2;
            float b0 = bias[col], b1 = bias[col + 1];
            g_reg[(size_t)row0 * DH + col]       = acc[mt][nt][0] + b0;
            g_reg[(size_t)row0 * DH + col + 1]   = acc[mt][nt][1] + b1;
            g_reg[(size_t)(row0 + 8) * DH + col]     = acc[mt][nt][2] + b0;
            g_reg[(size_t)(row0 + 8) * DH + col + 1] = acc[mt][nt][3] + b1;
        }
    }
}

// =====================================================================
// Stage 2: per-row LayerNorm (warp per row), affine with per-camera gamma/beta
// =====================================================================
__global__ __launch_bounds__(256) void ln_kernel(
    const float* __restrict__ gamma, const float* __restrict__ beta)
{
    int wglob = (blockIdx.x * blockDim.x + threadIdx.x) >> 5;
    int lane  = threadIdx.x & 31;
    if (wglob >= MTOT) return;
    int c = wglob & 3;
    const float* row = g_reg + (size_t)wglob * DH;
    float v[16], s = 0.f, s2 = 0.f;
    #pragma unroll
    for (int i = 0; i < 16; i++) {
        v[i] = row[lane + i * 32];
        s += v[i]; s2 += v[i] * v[i];
    }
    #pragma unroll
    for (int o = 16; o > 0; o >>= 1) {
        s  += __shfl_xor_sync(0xffffffffu, s,  o);
        s2 += __shfl_xor_sync(0xffffffffu, s2, o);
    }
    float mu   = s * (1.f / DH);
    float var  = s2 * (1.f / DH) - mu * mu;
    float rstd = rsqrtf(var + 1e-5f);
    float* orow = g_xn + (size_t)wglob * DH;
    const float* ga = gamma + c * DH;
    const float* be = beta  + c * DH;
    #pragma unroll
    for (int i = 0; i < 16; i++) {
        int k = lane + i * 32;
        orow[k] = (v[i] - mu) * rstd * ga[k] + be[k];
    }
}

// =====================================================================
// Stage 3: per-camera dual GEMM + SwiGLU, cp.async double-buffered.
// BM=128, BN=64, BK=32.  8 warps 4x2, warp 32x32, dual accumulators.
// =====================================================================
__global__ __launch_bounds__(256, 2) void gemm2_kernel(
    const float* __restrict__ Wg, const float* __restrict__ Wv)
{
    extern __shared__ float sm2[];
    float* As  = sm2;                       // [2][128*LDS_]
    float* Bgs = sm2 + 2 * 128 * LDS_;      // [2][64*LDS_]
    float* Bvs = Bgs + 2 * 64 * LDS_;       // [2][64*LDS_]

    int tid  = threadIdx.x;
    int bm   = blockIdx.y * 128;     // logical row (b index)
    int bn   = blockIdx.x * 64;      // f
    int c    = blockIdx.z;
    int warp = tid >> 5, lane = tid & 31;
    int wr = warp >> 1, wc = warp & 1;   // 4 x 2
    int wm = wr * 32,  wn = wc * 32;
    int g = lane >> 2, t = lane & 3;

    float accg[2][4][4], accv[2][4][4];
    #pragma unroll
    for (int i = 0; i < 2; i++)
        #pragma unroll
        for (int j = 0; j < 4; j++)
            #pragma unroll
            for (int k = 0; k < 4; k++) { accg[i][j][k] = 0.f; accv[i][j][k] = 0.f; }

    int lrow = tid >> 3;
    int lcol = (tid & 7) * 4;
    const float* wg0 = Wg + (size_t)c * DH * DH;
    const float* wv0 = Wv + (size_t)c * DH * DH;

    const int NK = DH / 32;   // 16

    {
        float* dA = As; float* dG = Bgs; float* dV = Bvs;
        #pragma unroll
        for (int it = 0; it < 4; it++) {
            int r = lrow + it * 32;
            cp16(&dA[r * LDS_ + lcol], g_xn + ((size_t)(bm + r) * 4 + c) * DH + lcol);
        }
        #pragma unroll
        for (int it = 0; it < 2; it++) {
            int r = lrow + it * 32;
            cp16(&dG[r * LDS_ + lcol], wg0 + (size_t)(bn + r) * DH + lcol);
            cp16(&dV[r * LDS_ + lcol], wv0 + (size_t)(bn + r) * DH + lcol);
        }
        cp_commit();
    }

    for (int i = 0; i < NK; i++) {
        if (i + 1 < NK) {
            int k0 = (i + 1) * 32;
            int b = (i + 1) & 1;
            float* dA = As  + b * 128 * LDS_;
            float* dG = Bgs + b * 64 * LDS_;
            float* dV = Bvs + b * 64 * LDS_;
            #pragma unroll
            for (int it = 0; it < 4; it++) {
                int r = lrow + it * 32;
                cp16(&dA[r * LDS_ + lcol], g_xn + ((size_t)(bm + r) * 4 + c) * DH + k0 + lcol);
            }
            #pragma unroll
            for (int it = 0; it < 2; it++) {
                int r = lrow + it * 32;
                cp16(&dG[r * LDS_ + lcol], wg0 + (size_t)(bn + r) * DH + k0 + lcol);
                cp16(&dV[r * LDS_ + lcol], wv0 + (size_t)(bn + r) * DH + k0 + lcol);
            }
            cp_commit();
            cp_wait1();
        } else {
            cp_wait0();
        }
        __syncthreads();

        int b = i & 1;
        const float* cA = As  + b * 128 * LDS_;
        const float* cG = Bgs + b * 64 * LDS_;
        const float* cV = Bvs + b * 64 * LDS_;
        #pragma unroll
        for (int kk = 0; kk < 32; kk += 8) {
            unsigned afr[2][4], bg[4][2], bv[4][2];
            #pragma unroll
            for (int mt = 0; mt < 2; mt++) {
                int r0 = wm + mt * 16;
                afr[mt][0] = f2tf(cA[(r0 + g    ) * LDS_ + kk + t]);
                afr[mt][1] = f2tf(cA[(r0 + 8 + g) * LDS_ + kk + t]);
                afr[mt][2] = f2tf(cA[(r0 + g    ) * LDS_ + kk + t + 4]);
                afr[mt][3] = f2tf(cA[(r0 + 8 + g) * LDS_ + kk + t + 4]);
            }
            #pragma unroll
            for (int nt = 0; nt < 4; nt++) {
                int n0 = wn + nt * 8;
                bg[nt][0] = f2tf(cG[(n0 + g) * LDS_ + kk + t]);
                bg[nt][1] = f2tf(cG[(n0 + g) * LDS_ + kk + t + 4]);
                bv[nt][0] = f2tf(cV[(n0 + g) * LDS_ + kk + t]);
                bv[nt][1] = f2tf(cV[(n0 + g) * LDS_ + kk + t + 4]);
            }
            #pragma unroll
            for (int mt = 0; mt < 2; mt++)
                #pragma unroll
                for (int nt = 0; nt < 4; nt++) {
                    mma_tf32(accg[mt][nt], afr[mt], bg[nt]);
                    mma_tf32(accv[mt][nt], afr[mt], bv[nt]);
                }
        }
        __syncthreads();
    }

    #pragma unroll
    for (int mt = 0; mt < 2; mt++) {
        #pragma unroll
        for (int nt = 0; nt < 4; nt++) {
            int row0 = bm + wm + mt * 16 + g;   // logical b index
            int col  = bn + wn + nt * 8 + t * 2;
            #pragma unroll
            for (int half = 0; half < 2; half++) {
                int rr = row0 + half * 8;
                float gte0 = accg[mt][nt][half * 2 + 0];
                float gte1 = accg[mt][nt][half * 2 + 1];
                float val0 = accv[mt][nt][half * 2 + 0];
                float val1 = accv[mt][nt][half * 2 + 1];
                float h0 = gte0 / (1.f + expf(-gte0)) * val0;
                float h1 = gte1 / (1.f + expf(-gte1)) * val1;
                float* dst = g_h + ((size_t)rr * 4 + c) * DH + col;
                dst[0] = h0; dst[1] = h1;
            }
        }
    }
}

// =====================================================================
// Stage 4: per-camera A[16384, 36] = h_c[16384, 512] @ w_out[c][36,512]^T
// BM=128, BN=40 (pad of 36), BK=32, cp.async double-buffered.
// =====================================================================
__global__ __launch_bounds__(256, 2) void gemm3_kernel(const float* __restrict__ Wo)
{
    extern __shared__ float sm3[];
    float* As = sm3;                  // [2][128*LDS_]
    float* Bs = sm3 + 2 * 128 * LDS_; // [2][40*LDS_]

    int tid  = threadIdx.x;
    int bm   = blockIdx.y * 128;
    int c    = blockIdx.z;
    int warp = tid >> 5, lane = tid & 31;
    int wm   = warp * 16;
    int g = lane >> 2, t = lane & 3;

    // zero the pad rows (36..39) of both B buffers once
    for (int i = tid; i < 2 * 4 * LDS_; i += 256) {
        int b = i / (4 * LDS_);
        int rem = i % (4 * LDS_);
        Bs[b * 40 * LDS_ + 36 * LDS_ + rem] = 0.f;
    }

    float acc[5][4];
    #pragma unroll
    for (int j = 0; j < 5; j++)
        #pragma unroll
        for (int k = 0; k < 4; k++) acc[j][k] = 0.f;

    int lrow = tid >> 3;
    int lcol = (tid & 7) * 4;
    const float* wo0 = Wo + (size_t)c * 36 * DH;

    const int NK = DH / 32;   // 16

    {
        #pragma unroll
        for (int it = 0; it < 4; it++) {
            int r = lrow + it * 32;
            cp16(&As[r * LDS_ + lcol], g_h + ((size_t)(bm + r) * 4 + c) * DH + lcol);
        }
        // B: 36 rows x 8 float4 cols = 288 items
        for (int i2 = tid; i2 < 288; i2 += 256) {
            int r = i2 >> 3, cc = (i2 & 7) * 4;
            cp16(&Bs[r * LDS_ + cc], wo0 + (size_t)r * DH + cc);
        }
        cp_commit();
    }

    for (int i = 0; i < NK; i++) {
        if (i + 1 < NK) {
            int k0 = (i + 1) * 32;
            int b = (i + 1) & 1;
            float* dA = As + b * 128 * LDS_;
            float* dB = Bs + b * 40 * LDS_;
            #pragma unroll
            for (int it = 0; it < 4; it++) {
                int r = lrow + it * 32;
                cp16(&dA[r * LDS_ + lcol], g_h + ((size_t)(bm + r) * 4 + c) * DH + k0 + lcol);
            }
            for (int i2 = tid; i2 < 288; i2 += 256) {
                int r = i2 >> 3, cc = (i2 & 7) * 4;
                cp16(&dB[r * LDS_ + cc], wo0 + (size_t)r * DH + k0 + cc);
            }
            cp_commit();
            cp_wait1();
        } else {
            cp_wait0();
        }
        __syncthreads();

        int b = i & 1;
        const float* cAc = As + b * 128 * LDS_;
        const float* cBc = Bs + b * 40 * LDS_;
        #pragma unroll
        for (int kk = 0; kk < 32; kk += 8) {
            unsigned afr[4], bfr[5][2];
            afr[0] = f2tf(cAc[(wm + g    ) * LDS_ + kk + t]);
            afr[1] = f2tf(cAc[(wm + 8 + g) * LDS_ + kk + t]);
            afr[2] = f2tf(cAc[(wm + g    ) * LDS_ + kk + t + 4]);
            afr[3] = f2tf(cAc[(wm + 8 + g) * LDS_ + kk + t + 4]);
            #pragma unroll
            for (int nt = 0; nt < 5; nt++) {
                int n0 = nt * 8;
                bfr[nt][0] = f2tf(cBc[(n0 + g) * LDS_ + kk + t]);
                bfr[nt][1] = f2tf(cBc[(n0 + g) * LDS_ + kk + t + 4]);
            }
            #pragma unroll
            for (int nt = 0; nt < 5; nt++)
                mma_tf32(acc[nt], afr, bfr[nt]);
        }
        __syncthreads();
    }

    #pragma unroll
    for (int nt = 0; nt < 5; nt++) {
        int col = nt * 8 + t * 2;
        if (col < 36) {
            int row0 = bm + wm + g;               // logical b index
            size_t base0 = ((size_t)row0 * 4 + c) * 36;
            size_t base1 = ((size_t)(row0 + 8) * 4 + c) * 36;
            g_A[base0 + col]     = acc[nt][0];
            g_A[base0 + col + 1] = acc[nt][1];
            g_A[base1 + col]     = acc[nt][2];
            g_A[base1 + col + 1] = acc[nt][3];
        }
    }
}

// =====================================================================
// Stage 5: skew-symmetrize, Frobenius clip, expm (scale-square, Taylor 12),
// write out[C, B, 6, 6]. One thread per matrix.
// =====================================================================
__global__ __launch_bounds__(128) void expm_kernel(float* __restrict__ out)
{
    int m = blockIdx.x * blockDim.x + threadIdx.x;
    if (m >= MTOT) return;
    int c = m & 3, b = m >> 2;

    const float* src = g_A + (size_t)m * 36;
    float raw[36];
    #pragma unroll
    for (int i = 0; i < 36; i++) raw[i] = src[i];

    float A[36]; float ss = 0.f;
    #pragma unroll
    for (int i = 0; i < 6; i++)
        #pragma unroll
        for (int j = 0; j < 6; j++) {
            float v = raw[i * 6 + j] - raw[j * 6 + i];
            A[i * 6 + j] = v; ss += v * v;
        }
    float frob  = sqrtf(ss);
    float scale = fminf(frob, 3.0f) / fmaxf(frob, 1e-8f);

    float As[36];
    #pragma unroll
    for (int i = 0; i < 36; i++) As[i] = A[i] * scale * 0.0625f;  // /16

    float E[36], term[36];
    #pragma unroll
    for (int i = 0; i < 36; i++) { E[i] = (i % 7 == 0) ? 1.f : 0.f; term[i] = E[i]; }

    #pragma unroll 1
    for (int k = 1; k <= 12; k++) {
        float nt[36];
        float inv = 1.f / (float)k;
        #pragma unroll
        for (int i = 0; i < 6; i++)
            #pragma unroll
            for (int j = 0; j < 6; j++) {
                float sacc = 0.f;
                #pragma unroll
                for (int l = 0; l < 6; l++) sacc += term[i * 6 + l] * As[l * 6 + j];
                nt[i * 6 + j] = sacc * inv;
            }
        #pragma unroll
        for (int i = 0; i < 36; i++) { term[i] = nt[i]; E[i] += nt[i]; }
    }
    #pragma unroll 1
    for (int s = 0; s < 4; s++) {
        float nt[36];
        #pragma unroll
        for (int i = 0; i < 6; i++)
            #pragma unroll
            for (int j = 0; j < 6; j++) {
                float sacc = 0.f;
                #pragma unroll
                for (int l = 0; l < 6; l++) sacc += E[i * 6 + l] * E[l * 6 + j];
                nt[i * 6 + j] = sacc;
            }
        #pragma unroll
        for (int i = 0; i < 36; i++) E[i] = nt[i];
    }

    float* dst = out + ((size_t)c * B_SZ + b) * 36;
    #pragma unroll
    for (int i = 0; i < 36; i++) dst[i] = E[i];
}

// =====================================================================
extern "C" void kernel_launch(void* const* d_in, const int* in_sizes, int n_in,
                              void* d_out, int out_size)
{
    const float* thumb  = (const float*)d_in[0];
    const float* proj_w = (const float*)d_in[1];
    const float* proj_b = (const float*)d_in[2];
    const float* gamma  = (const float*)d_in[3];
    const float* beta   = (const float*)d_in[4];
    const float* w_gate = (const float*)d_in[5];
    const float* w_val  = (const float*)d_in[6];
    const float* w_out  = (const float*)d_in[7];
    float* out = (float*)d_out;

    (void)in_sizes; (void)n_in; (void)out_size;

    const int SM1 = 2 * 128 * LDS_ * 4 * 2;                 // 73728
    const int SM2 = (2 * 128 * LDS_ + 4 * 64 * LDS_) * 4;   // 73728
    const int SM3 = (2 * 128 * LDS_ + 2 * 40 * LDS_) * 4;   // 48384

    cudaFuncSetAttribute(gemm1_kernel, cudaFuncAttributeMaxDynamicSharedMemorySize, SM1);
    cudaFuncSetAttribute(gemm2_kernel, cudaFuncAttributeMaxDynamicSharedMemorySize, SM2);
    cudaFuncSetAttribute(gemm3_kernel, cudaFuncAttributeMaxDynamicSharedMemorySize, SM3);

    gemm1_kernel<<<dim3(4, 512), 256, SM1>>>(thumb, proj_w, proj_b);
    ln_kernel<<<MTOT / 8, 256>>>(gamma, beta);
    gemm2_kernel<<<dim3(8, 128, 4), 256, SM2>>>(w_gate, w_val);
    gemm3_kernel<<<dim3(1, 128, 4), 256, SM3>>>(w_out);
    expm_kernel<<<MTOT / 128, 128>>>(out);
}

// round 5
// speedup vs baseline: 1.2219x; 1.0188x over previous
#include <cuda_runtime.h>
#include <math.h>
#include <stdint.h>

#define B_SZ   16384
#define C_CAM  4
#define DBB    2048
#define DH     512
#define MTOT   (B_SZ * C_CAM)

// -------- device-global scratch (no allocations allowed) --------
__device__ float g_reg[(size_t)MTOT * DH];
__device__ float g_xn [(size_t)MTOT * DH];
__device__ float g_h  [(size_t)MTOT * DH];
__device__ float g_A  [(size_t)MTOT * 36];
__device__ float g_pw [(size_t)DH * DBB];            // rna-rounded proj_w
__device__ float g_wg [(size_t)C_CAM * DH * DH];     // rna-rounded w_gate
__device__ float g_wv [(size_t)C_CAM * DH * DH];     // rna-rounded w_val
__device__ float g_wo [(size_t)C_CAM * 36 * DH];     // rna-rounded w_out

// -------- helpers --------
__device__ __forceinline__ unsigned f2tf(float x) {
    unsigned u; asm("cvt.rna.tf32.f32 %0, %1;" : "=r"(u) : "f"(x)); return u;
}
__device__ __forceinline__ void mma_tf32(float d[4], const unsigned a[4], const unsigned b[2]) {
    asm volatile(
        "mma.sync.aligned.m16n8k8.row.col.f32.tf32.tf32.f32 "
        "{%0,%1,%2,%3}, {%4,%5,%6,%7}, {%8,%9}, {%0,%1,%2,%3};\n"
        : "+f"(d[0]), "+f"(d[1]), "+f"(d[2]), "+f"(d[3])
        : "r"(a[0]), "r"(a[1]), "r"(a[2]), "r"(a[3]), "r"(b[0]), "r"(b[1]));
}
__device__ __forceinline__ void cp16(float* s, const float* g) {
    unsigned a = (unsigned)__cvta_generic_to_shared(s);
    asm volatile("cp.async.cg.shared.global [%0], [%1], 16;\n" :: "r"(a), "l"(g));
}
__device__ __forceinline__ void cp_commit() { asm volatile("cp.async.commit_group;\n" ::: "memory"); }
__device__ __forceinline__ void cp_wait1()  { asm volatile("cp.async.wait_group 1;\n" ::: "memory"); }
__device__ __forceinline__ void cp_wait0()  { asm volatile("cp.async.wait_group 0;\n" ::: "memory"); }

#define LDS_ 36   // 32 + 4 pad floats

// =====================================================================
// Stage 0: rna-round all weight matrices (proj_w, w_gate, w_val: 1048576
// each; w_out: 73728). Blocks 0..4095 cover the big three; 4096..4383 w_out.
// =====================================================================
__global__ __launch_bounds__(256) void round_weights(
    const float* __restrict__ pw, const float* __restrict__ wg,
    const float* __restrict__ wv, const float* __restrict__ wo)
{
    int bi = blockIdx.x;
    if (bi < 4096) {
        int i = bi * 256 + threadIdx.x;
        g_pw[i] = __uint_as_float(f2tf(pw[i]));
        g_wg[i] = __uint_as_float(f2tf(wg[i]));
        g_wv[i] = __uint_as_float(f2tf(wv[i]));
    } else {
        int i = (bi - 4096) * 256 + threadIdx.x;
        g_wo[i] = __uint_as_float(f2tf(wo[i]));
    }
}

// =====================================================================
// Stage 1: reg[65536,512] = thumb[65536,2048] @ proj_w^T + bias
// BM=128, BN=128, BK=32, 3-stage cp.async, one barrier per tile.
// 8 warps 2x4, warp tile 64x32. A gets in-loop rna cvt; B pre-rounded.
// =====================================================================
__global__ __launch_bounds__(256, 2) void gemm1_kernel(
    const float* __restrict__ T, const float* __restrict__ bias)
{
    extern __shared__ float sm1[];
    float* As = sm1;                    // [3][128*LDS_]
    float* Bs = sm1 + 3 * 128 * LDS_;   // [3][128*LDS_]

    int tid  = threadIdx.x;
    int bm   = blockIdx.y * 128;
    int bn   = blockIdx.x * 128;
    int warp = tid >> 5, lane = tid & 31;
    int wr = warp >> 2, wc = warp & 3;
    int wm = wr * 64,  wn = wc * 32;
    int g = lane >> 2, t = lane & 3;

    float acc[4][4][4];
    #pragma unroll
    for (int i = 0; i < 4; i++)
        #pragma unroll
        for (int j = 0; j < 4; j++)
            #pragma unroll
            for (int k = 0; k < 4; k++) acc[i][j][k] = 0.f;

    int lrow = tid >> 3;            // 0..31
    int lcol = (tid & 7) * 4;       // 0..28
    const int NK = DBB / 32;        // 64

    // prologue: stages 0 and 1
    #pragma unroll
    for (int s = 0; s < 2; s++) {
        float* dA = As + s * 128 * LDS_;
        float* dB = Bs + s * 128 * LDS_;
        int k0 = s * 32;
        #pragma unroll
        for (int it = 0; it < 4; it++) {
            int r = lrow + it * 32;
            cp16(&dA[r * LDS_ + lcol], T    + (size_t)(bm + r) * DBB + k0 + lcol);
            cp16(&dB[r * LDS_ + lcol], g_pw + (size_t)(bn + r) * DBB + k0 + lcol);
        }
        cp_commit();
    }

    int slot = 0, nslot = 2;
    for (int i = 0; i < NK; i++) {
        cp_wait1();
        __syncthreads();

        if (i + 2 < NK) {
            int k0 = (i + 2) * 32;
            float* dA = As + nslot * 128 * LDS_;
            float* dB = Bs + nslot * 128 * LDS_;
            #pragma unroll
            for (int it = 0; it < 4; it++) {
                int r = lrow + it * 32;
                cp16(&dA[r * LDS_ + lcol], T    + (size_t)(bm + r) * DBB + k0 + lcol);
                cp16(&dB[r * LDS_ + lcol], g_pw + (size_t)(bn + r) * DBB + k0 + lcol);
            }
        }
        cp_commit();

        const float*    cA = As + slot * 128 * LDS_;
        const unsigned* cB = (const unsigned*)(Bs + slot * 128 * LDS_);
        #pragma unroll
        for (int kk = 0; kk < 32; kk += 8) {
            unsigned afr[4][4], bfr[4][2];
            #pragma unroll
            for (int mt = 0; mt < 4; mt++) {
                int r0 = wm + mt * 16;
                afr[mt][0] = f2tf(cA[(r0 + g    ) * LDS_ + kk + t]);
                afr[mt][1] = f2tf(cA[(r0 + 8 + g) * LDS_ + kk + t]);
                afr[mt][2] = f2tf(cA[(r0 + g    ) * LDS_ + kk + t + 4]);
                afr[mt][3] = f2tf(cA[(r0 + 8 + g) * LDS_ + kk + t + 4]);
            }
            #pragma unroll
            for (int nt = 0; nt < 4; nt++) {
                int n0 = wn + nt * 8;
                bfr[nt][0] = cB[(n0 + g) * LDS_ + kk + t];
                bfr[nt][1] = cB[(n0 + g) * LDS_ + kk + t + 4];
            }
            #pragma unroll
            for (int mt = 0; mt < 4; mt++)
                #pragma unroll
                for (int nt = 0; nt < 4; nt++)
                    mma_tf32(acc[mt][nt], afr[mt], bfr[nt]);
        }
        slot = (slot == 2) ? 0 : slot + 1;
        nslot = (nslot == 2) ? 0 : nslot + 1;
    }

    #pragma unroll
    for (int mt = 0; mt < 4; mt++) {
        #pragma unroll
        for (int nt = 0; nt < 4; nt++) {
            int row0 = bm + wm + mt * 16 + g;
            int col  = bn + wn + nt * 8 + t * 2;
            float b0 = bias[col], b1 = bias[col + 1];
            g_reg[(size_t)row0 * DH + col]           = acc[mt][nt][0] + b0;
            g_reg[(size_t)row0 * DH + col + 1]       = acc[mt][nt][1] + b1;
            g_reg[(size_t)(row0 + 8) * DH + col]     = acc[mt][nt][2] + b0;
            g_reg[(size_t)(row0 + 8) * DH + col + 1] = acc[mt][nt][3] + b1;
        }
    }
}

// =====================================================================
// Stage 2: LayerNorm (warp/row), rna-rounded output
// =====================================================================
__global__ __launch_bounds__(256) void ln_kernel(
    const float* __restrict__ gamma, const float* __restrict__ beta)
{
    int wglob = (blockIdx.x * blockDim.x + threadIdx.x) >> 5;
    int lane  = threadIdx.x & 31;
    if (wglob >= MTOT) return;
    int c = wglob & 3;
    const float* row = g_reg + (size_t)wglob * DH;
    float v[16], s = 0.f, s2 = 0.f;
    #pragma unroll
    for (int i = 0; i < 16; i++) {
        v[i] = row[lane + i * 32];
        s += v[i]; s2 += v[i] * v[i];
    }
    #pragma unroll
    for (int o = 16; o > 0; o >>= 1) {
        s  += __shfl_xor_sync(0xffffffffu, s,  o);
        s2 += __shfl_xor_sync(0xffffffffu, s2, o);
    }
    float mu   = s * (1.f / DH);
    float var  = s2 * (1.f / DH) - mu * mu;
    float rstd = rsqrtf(var + 1e-5f);
    float* orow = g_xn + (size_t)wglob * DH;
    const float* ga = gamma + c * DH;
    const float* be = beta  + c * DH;
    #pragma unroll
    for (int i = 0; i < 16; i++) {
        int k = lane + i * 32;
        float xn = (v[i] - mu) * rstd * ga[k] + be[k];
        orow[k] = __uint_as_float(f2tf(xn));
    }
}

// =====================================================================
// Stage 3: per-camera dual GEMM + SwiGLU. BM=128, BN=64, BK=32,
// 3-stage cp.async, one barrier per tile. No cvts (all inputs pre-rounded).
// =====================================================================
__global__ __launch_bounds__(256, 2) void gemm2_kernel()
{
    extern __shared__ float sm2[];
    float* As  = sm2;                        // [3][128*LDS_]
    float* Bgs = sm2 + 3 * 128 * LDS_;       // [3][64*LDS_]
    float* Bvs = Bgs + 3 * 64 * LDS_;        // [3][64*LDS_]

    int tid  = threadIdx.x;
    int bm   = blockIdx.y * 128;
    int bn   = blockIdx.x * 64;
    int c    = blockIdx.z;
    int warp = tid >> 5, lane = tid & 31;
    int wr = warp >> 1, wc = warp & 1;
    int wm = wr * 32,  wn = wc * 32;
    int g = lane >> 2, t = lane & 3;

    float accg[2][4][4], accv[2][4][4];
    #pragma unroll
    for (int i = 0; i < 2; i++)
        #pragma unroll
        for (int j = 0; j < 4; j++)
            #pragma unroll
            for (int k = 0; k < 4; k++) { accg[i][j][k] = 0.f; accv[i][j][k] = 0.f; }

    int lrow = tid >> 3;
    int lcol = (tid & 7) * 4;
    const float* wg0 = g_wg + (size_t)c * DH * DH;
    const float* wv0 = g_wv + (size_t)c * DH * DH;
    const int NK = DH / 32;   // 16

    #pragma unroll
    for (int s = 0; s < 2; s++) {
        int k0 = s * 32;
        float* dA = As  + s * 128 * LDS_;
        float* dG = Bgs + s * 64 * LDS_;
        float* dV = Bvs + s * 64 * LDS_;
        #pragma unroll
        for (int it = 0; it < 4; it++) {
            int r = lrow + it * 32;
            cp16(&dA[r * LDS_ + lcol], g_xn + ((size_t)(bm + r) * 4 + c) * DH + k0 + lcol);
        }
        #pragma unroll
        for (int it = 0; it < 2; it++) {
            int r = lrow + it * 32;
            cp16(&dG[r * LDS_ + lcol], wg0 + (size_t)(bn + r) * DH + k0 + lcol);
            cp16(&dV[r * LDS_ + lcol], wv0 + (size_t)(bn + r) * DH + k0 + lcol);
        }
        cp_commit();
    }

    int slot = 0, nslot = 2;
    for (int i = 0; i < NK; i++) {
        cp_wait1();
        __syncthreads();

        if (i + 2 < NK) {
            int k0 = (i + 2) * 32;
            float* dA = As  + nslot * 128 * LDS_;
            float* dG = Bgs + nslot * 64 * LDS_;
            float* dV = Bvs + nslot * 64 * LDS_;
            #pragma unroll
            for (int it = 0; it < 4; it++) {
                int r = lrow + it * 32;
                cp16(&dA[r * LDS_ + lcol], g_xn + ((size_t)(bm + r) * 4 + c) * DH + k0 + lcol);
            }
            #pragma unroll
            for (int it = 0; it < 2; it++) {
                int r = lrow + it * 32;
                cp16(&dG[r * LDS_ + lcol], wg0 + (size_t)(bn + r) * DH + k0 + lcol);
                cp16(&dV[r * LDS_ + lcol], wv0 + (size_t)(bn + r) * DH + k0 + lcol);
            }
        }
        cp_commit();

        const unsigned* cA = (const unsigned*)(As  + slot * 128 * LDS_);
        const unsigned* cG = (const unsigned*)(Bgs + slot * 64 * LDS_);
        const unsigned* cV = (const unsigned*)(Bvs + slot * 64 * LDS_);
        #pragma unroll
        for (int kk = 0; kk < 32; kk += 8) {
            unsigned afr[2][4], bg[4][2], bv[4][2];
            #pragma unroll
            for (int mt = 0; mt < 2; mt++) {
                int r0 = wm + mt * 16;
                afr[mt][0] = cA[(r0 + g    ) * LDS_ + kk + t];
                afr[mt][1] = cA[(r0 + 8 + g) * LDS_ + kk + t];
                afr[mt][2] = cA[(r0 + g    ) * LDS_ + kk + t + 4];
                afr[mt][3] = cA[(r0 + 8 + g) * LDS_ + kk + t + 4];
            }
            #pragma unroll
            for (int nt = 0; nt < 4; nt++) {
                int n0 = wn + nt * 8;
                bg[nt][0] = cG[(n0 + g) * LDS_ + kk + t];
                bg[nt][1] = cG[(n0 + g) * LDS_ + kk + t + 4];
                bv[nt][0] = cV[(n0 + g) * LDS_ + kk + t];
                bv[nt][1] = cV[(n0 + g) * LDS_ + kk + t + 4];
            }
            #pragma unroll
            for (int mt = 0; mt < 2; mt++)
                #pragma unroll
                for (int nt = 0; nt < 4; nt++) {
                    mma_tf32(accg[mt][nt], afr[mt], bg[nt]);
                    mma_tf32(accv[mt][nt], afr[mt], bv[nt]);
                }
        }
        slot = (slot == 2) ? 0 : slot + 1;
        nslot = (nslot == 2) ? 0 : nslot + 1;
    }

    #pragma unroll
    for (int mt = 0; mt < 2; mt++) {
        #pragma unroll
        for (int nt = 0; nt < 4; nt++) {
            int row0 = bm + wm + mt * 16 + g;
            int col  = bn + wn + nt * 8 + t * 2;
            #pragma unroll
            for (int half = 0; half < 2; half++) {
                int rr = row0 + half * 8;
                float gte0 = accg[mt][nt][half * 2 + 0];
                float gte1 = accg[mt][nt][half * 2 + 1];
                float val0 = accv[mt][nt][half * 2 + 0];
                float val1 = accv[mt][nt][half * 2 + 1];
                float h0 = gte0 / (1.f + expf(-gte0)) * val0;
                float h1 = gte1 / (1.f + expf(-gte1)) * val1;
                float* dst = g_h + ((size_t)rr * 4 + c) * DH + col;
                dst[0] = __uint_as_float(f2tf(h0));
                dst[1] = __uint_as_float(f2tf(h1));
            }
        }
    }
}

// =====================================================================
// Stage 4: per-camera A[16384,36] = h_c @ w_out^T. 2-stage, no cvts.
// =====================================================================
__global__ __launch_bounds__(256, 2) void gemm3_kernel()
{
    extern __shared__ float sm3[];
    float* As = sm3;
    float* Bs = sm3 + 2 * 128 * LDS_;

    int tid  = threadIdx.x;
    int bm   = blockIdx.y * 128;
    int c    = blockIdx.z;
    int warp = tid >> 5, lane = tid & 31;
    int wm   = warp * 16;
    int g = lane >> 2, t = lane & 3;

    for (int i = tid; i < 2 * 4 * LDS_; i += 256) {
        int b = i / (4 * LDS_);
        int rem = i % (4 * LDS_);
        Bs[b * 40 * LDS_ + 36 * LDS_ + rem] = 0.f;
    }

    float acc[5][4];
    #pragma unroll
    for (int j = 0; j < 5; j++)
        #pragma unroll
        for (int k = 0; k < 4; k++) acc[j][k] = 0.f;

    int lrow = tid >> 3;
    int lcol = (tid & 7) * 4;
    const float* wo0 = g_wo + (size_t)c * 36 * DH;
    const int NK = DH / 32;

    {
        #pragma unroll
        for (int it = 0; it < 4; it++) {
            int r = lrow + it * 32;
            cp16(&As[r * LDS_ + lcol], g_h + ((size_t)(bm + r) * 4 + c) * DH + lcol);
        }
        for (int i2 = tid; i2 < 288; i2 += 256) {
            int r = i2 >> 3, cc = (i2 & 7) * 4;
            cp16(&Bs[r * LDS_ + cc], wo0 + (size_t)r * DH + cc);
        }
        cp_commit();
    }

    for (int i = 0; i < NK; i++) {
        if (i + 1 < NK) {
            int k0 = (i + 1) * 32;
            int b = (i + 1) & 1;
            float* dA = As + b * 128 * LDS_;
            float* dB = Bs + b * 40 * LDS_;
            #pragma unroll
            for (int it = 0; it < 4; it++) {
                int r = lrow + it * 32;
                cp16(&dA[r * LDS_ + lcol], g_h + ((size_t)(bm + r) * 4 + c) * DH + k0 + lcol);
            }
            for (int i2 = tid; i2 < 288; i2 += 256) {
                int r = i2 >> 3, cc = (i2 & 7) * 4;
                cp16(&dB[r * LDS_ + cc], wo0 + (size_t)r * DH + k0 + cc);
            }
            cp_commit(); cp_wait1();
        } else {
            cp_wait0();
        }
        __syncthreads();

        int b = i & 1;
        const unsigned* cAc = (const unsigned*)(As + b * 128 * LDS_);
        const unsigned* cBc = (const unsigned*)(Bs + b * 40 * LDS_);
        #pragma unroll
        for (int kk = 0; kk < 32; kk += 8) {
            unsigned afr[4], bfr[5][2];
            afr[0] = cAc[(wm + g    ) * LDS_ + kk + t];
            afr[1] = cAc[(wm + 8 + g) * LDS_ + kk + t];
            afr[2] = cAc[(wm + g    ) * LDS_ + kk + t + 4];
            afr[3] = cAc[(wm + 8 + g) * LDS_ + kk + t + 4];
            #pragma unroll
            for (int nt = 0; nt < 5; nt++) {
                int nn = nt * 8;
                bfr[nt][0] = cBc[(nn + g) * LDS_ + kk + t];
                bfr[nt][1] = cBc[(nn + g) * LDS_ + kk + t + 4];
            }
            #pragma unroll
            for (int nt = 0; nt < 5; nt++)
                mma_tf32(acc[nt], afr, bfr[nt]);
        }
        __syncthreads();
    }

    #pragma unroll
    for (int nt = 0; nt < 5; nt++) {
        int col = nt * 8 + t * 2;
        if (col < 36) {
            int row0 = bm + wm + g;
            size_t base0 = ((size_t)row0 * 4 + c) * 36;
            size_t base1 = ((size_t)(row0 + 8) * 4 + c) * 36;
            g_A[base0 + col]     = acc[nt][0];
            g_A[base0 + col + 1] = acc[nt][1];
            g_A[base1 + col]     = acc[nt][2];
            g_A[base1 + col + 1] = acc[nt][3];
        }
    }
}

// =====================================================================
// Stage 5: skew + clip + expm (scale-square Taylor 12), out[C,B,6,6]
// =====================================================================
__global__ __launch_bounds__(128) void expm_kernel(float* __restrict__ out)
{
    int m = blockIdx.x * blockDim.x + threadIdx.x;
    if (m >= MTOT) return;
    int c = m & 3, b = m >> 2;

    const float* src = g_A + (size_t)m * 36;
    float raw[36];
    #pragma unroll
    for (int i = 0; i < 36; i++) raw[i] = src[i];

    float A[36]; float ss = 0.f;
    #pragma unroll
    for (int i = 0; i < 6; i++)
        #pragma unroll
        for (int j = 0; j < 6; j++) {
            float v = raw[i * 6 + j] - raw[j * 6 + i];
            A[i * 6 + j] = v; ss += v * v;
        }
    float frob  = sqrtf(ss);
    float scale = fminf(frob, 3.0f) / fmaxf(frob, 1e-8f);

    float As[36];
    #pragma unroll
    for (int i = 0; i < 36; i++) As[i] = A[i] * scale * 0.0625f;

    float E[36], term[36];
    #pragma unroll
    for (int i = 0; i < 36; i++) { E[i] = (i % 7 == 0) ? 1.f : 0.f; term[i] = E[i]; }

    #pragma unroll 1
    for (int k = 1; k <= 12; k++) {
        float nt[36];
        float inv = 1.f / (float)k;
        #pragma unroll
        for (int i = 0; i < 6; i++)
            #pragma unroll
            for (int j = 0; j < 6; j++) {
                float sacc = 0.f;
                #pragma unroll
                for (int l = 0; l < 6; l++) sacc += term[i * 6 + l] * As[l * 6 + j];
                nt[i * 6 + j] = sacc * inv;
            }
        #pragma unroll
        for (int i = 0; i < 36; i++) { term[i] = nt[i]; E[i] += nt[i]; }
    }
    #pragma unroll 1
    for (int s = 0; s < 4; s++) {
        float nt[36];
        #pragma unroll
        for (int i = 0; i < 6; i++)
            #pragma unroll
            for (int j = 0; j < 6; j++) {
                float sacc = 0.f;
                #pragma unroll
                for (int l = 0; l < 6; l++) sacc += E[i * 6 + l] * E[l * 6 + j];
                nt[i * 6 + j] = sacc;
            }
        #pragma unroll
        for (int i = 0; i < 36; i++) E[i] = nt[i];
    }

    float* dst = out + ((size_t)c * B_SZ + b) * 36;
    #pragma unroll
    for (int i = 0; i < 36; i++) dst[i] = E[i];
}

// =====================================================================
extern "C" void kernel_launch(void* const* d_in, const int* in_sizes, int n_in,
                              void* d_out, int out_size)
{
    const float* thumb  = (const float*)d_in[0];
    const float* proj_w = (const float*)d_in[1];
    const float* proj_b = (const float*)d_in[2];
    const float* gamma  = (const float*)d_in[3];
    const float* beta   = (const float*)d_in[4];
    const float* w_gate = (const float*)d_in[5];
    const float* w_val  = (const float*)d_in[6];
    const float* w_out  = (const float*)d_in[7];
    float* out = (float*)d_out;

    (void)in_sizes; (void)n_in; (void)out_size;

    const int SM1 = 3 * 2 * 128 * LDS_ * 4;                 // 110592
    const int SM2 = (3 * 128 * LDS_ + 6 * 64 * LDS_) * 4;   // 110592
    const int SM3 = (2 * 128 * LDS_ + 2 * 40 * LDS_) * 4;   // 48384

    cudaFuncSetAttribute(gemm1_kernel, cudaFuncAttributeMaxDynamicSharedMemorySize, SM1);
    cudaFuncSetAttribute(gemm2_kernel, cudaFuncAttributeMaxDynamicSharedMemorySize, SM2);
    cudaFuncSetAttribute(gemm3_kernel, cudaFuncAttributeMaxDynamicSharedMemorySize, SM3);

    round_weights<<<4384, 256>>>(proj_w, w_gate, w_val, w_out);
    gemm1_kernel<<<dim3(4, 512), 256, SM1>>>(thumb, proj_b);
    ln_kernel<<<MTOT / 8, 256>>>(gamma, beta);
    gemm2_kernel<<<dim3(8, 128, 4), 256, SM2>>>();
    gemm3_kernel<<<dim3(1, 128, 4), 256, SM3>>>();
    expm_kernel<<<MTOT / 128, 128>>>(out);
}